// round 14
// baseline (speedup 1.0000x reference)
#include <cuda_runtime.h>
#include <cuda_bf16.h>
#include <cstdint>

#define NN    8192
#define SDIM  2
#define JDIM  256
#define COUT  32

#define BM 128
#define BN 128
#define BK 32
#define KT 512          // SDIM*NN / BK
#define SK 40           // padded smem row stride in bf16 elems (80 B, 16B-aligned)

// pipeline
#define NSTAGES  4
#define AHI_OFF  0
#define ALO_OFF  10240
#define BHI_OFF  20480
#define BLO_OFF  30720
#define ST_BYTES 40960
#define SMEM_TOTAL (NSTAGES * ST_BYTES)   // 160 KB dynamic

// Pre-split operands in gmem (static device scratch; no allocs allowed)
__device__ __align__(256) __nv_bfloat16 g_A_hi[(size_t)SDIM * NN * NN];   // 268 MB
__device__ __align__(256) __nv_bfloat16 g_A_lo[(size_t)SDIM * NN * NN];   // 268 MB
__device__ __align__(256) __nv_bfloat16 g_Yt_hi[(size_t)SDIM * JDIM * NN];
__device__ __align__(256) __nv_bfloat16 g_Yt_lo[(size_t)SDIM * JDIM * NN];

// ---------------------------------------------------------------------------
// helpers
// ---------------------------------------------------------------------------
__device__ __forceinline__ uint32_t smem_u32(const void* p) {
    uint32_t a;
    asm("{ .reg .u64 t; cvta.to.shared.u64 t, %1; cvt.u32.u64 %0, t; }"
        : "=r"(a) : "l"(p));
    return a;
}

// pack two floats to bf16x2 (element0 = a, element1 = b)
__device__ __forceinline__ uint32_t bf2(float a, float b) {
    uint32_t r;
    asm("cvt.rn.bf16x2.f32 %0, %1, %2;" : "=r"(r) : "f"(b), "f"(a));
    return r;
}

__device__ __forceinline__ void cp_async16(uint32_t dst, const void* src) {
    asm volatile("cp.async.cg.shared.global [%0], [%1], 16;"
                 :: "r"(dst), "l"(src) : "memory");
}
__device__ __forceinline__ void cp_commit() {
    asm volatile("cp.async.commit_group;" ::: "memory");
}
__device__ __forceinline__ void cp_wait2() {
    asm volatile("cp.async.wait_group 2;" ::: "memory");
}

__device__ __forceinline__ void ldsm4(uint32_t* r, uint32_t addr) {
    asm volatile("ldmatrix.sync.aligned.m8n8.x4.shared.b16 {%0,%1,%2,%3}, [%4];"
                 : "=r"(r[0]), "=r"(r[1]), "=r"(r[2]), "=r"(r[3]) : "r"(addr));
}

__device__ __forceinline__ void mma_bf16(float* c, const uint32_t* a, const uint32_t* b) {
    asm volatile(
        "mma.sync.aligned.m16n8k16.row.col.f32.bf16.bf16.f32 "
        "{%0,%1,%2,%3},{%4,%5,%6,%7},{%8,%9},{%0,%1,%2,%3};"
        : "+f"(c[0]), "+f"(c[1]), "+f"(c[2]), "+f"(c[3])
        : "r"(a[0]), "r"(a[1]), "r"(a[2]), "r"(a[3]), "r"(b[0]), "r"(b[1]));
}

// ---------------------------------------------------------------------------
// Prep 1: split supports (fp32) -> g_A_hi/g_A_lo (bf16). Pure streaming.
// grid 65536 x 256 threads, 8 elems/thread.
// ---------------------------------------------------------------------------
__global__ __launch_bounds__(256)
void prep_Asplit_kernel(const float* __restrict__ sup) {
    const size_t i = ((size_t)blockIdx.x * 256 + threadIdx.x) * 8;
    float4 f0 = *(const float4*)(sup + i);
    float4 f1 = *(const float4*)(sup + i + 4);

    uint32_t h01 = bf2(f0.x, f0.y);
    uint32_t h23 = bf2(f0.z, f0.w);
    uint32_t h45 = bf2(f1.x, f1.y);
    uint32_t h67 = bf2(f1.z, f1.w);
    float l0 = f0.x - __uint_as_float(h01 << 16);
    float l1 = f0.y - __uint_as_float(h01 & 0xffff0000u);
    float l2 = f0.z - __uint_as_float(h23 << 16);
    float l3 = f0.w - __uint_as_float(h23 & 0xffff0000u);
    float l4 = f1.x - __uint_as_float(h45 << 16);
    float l5 = f1.y - __uint_as_float(h45 & 0xffff0000u);
    float l6 = f1.z - __uint_as_float(h67 << 16);
    float l7 = f1.w - __uint_as_float(h67 & 0xffff0000u);

    *(uint4*)(g_A_hi + i) = make_uint4(h01, h23, h45, h67);
    *(uint4*)(g_A_lo + i) = make_uint4(bf2(l0, l1), bf2(l2, l3),
                                       bf2(l4, l5), bf2(l6, l7));
}

// ---------------------------------------------------------------------------
// Prep 2: Yt_hi/lo[s][j][k] = split_bf16( sum_c x[b,k,c] * W[s,o,c] ),
//         j = b*32+o.  grid (64 kblocks, 8 b, 2 s), 256 threads.
// ---------------------------------------------------------------------------
__global__ void prep_Yt_kernel(const float* __restrict__ x,
                               const float* __restrict__ W) {
    __shared__ float Wsh[COUT][33];
    __shared__ __align__(16) float xsh[128][32];
    __shared__ __align__(16) __nv_bfloat16 yhi[COUT][128];
    __shared__ __align__(16) __nv_bfloat16 ylo[COUT][128];

    const int s  = blockIdx.z;
    const int b  = blockIdx.y;
    const int kb = blockIdx.x;
    const int t  = threadIdx.x;

    for (int i = t; i < 1024; i += 256) Wsh[i >> 5][i & 31] = W[s * 1024 + i];

    const float4* xbase = (const float4*)(x + ((size_t)b * NN + (size_t)kb * 128) * 32);
#pragma unroll
    for (int i = 0; i < 4; i++) {
        int f = t + 256 * i;
        ((float4*)&xsh[0][0])[f] = xbase[f];
    }
    __syncthreads();

    const int o = t & 31;
#pragma unroll
    for (int i = 0; i < 16; i++) {
        int ki = (t >> 5) + i * 8;
        float sum = 0.0f;
#pragma unroll
        for (int c = 0; c < 32; c++) sum += xsh[ki][c] * Wsh[o][c];
        __nv_bfloat16 h = __float2bfloat16(sum);
        float hf = __bfloat162float(h);
        __nv_bfloat16 l = __float2bfloat16(sum - hf);
        yhi[o][ki] = h;
        ylo[o][ki] = l;
    }
    __syncthreads();

    const int oo  = t >> 3;
    const int seg = t & 7;
    size_t base = ((size_t)(s * JDIM + b * 32 + oo)) * NN + (size_t)kb * 128 + seg * 16;
    *(uint4*)(&g_Yt_hi[base])     = *(const uint4*)(&yhi[oo][seg * 16]);
    *(uint4*)(&g_Yt_hi[base + 8]) = *(const uint4*)(&yhi[oo][seg * 16 + 8]);
    *(uint4*)(&g_Yt_lo[base])     = *(const uint4*)(&ylo[oo][seg * 16]);
    *(uint4*)(&g_Yt_lo[base + 8]) = *(const uint4*)(&ylo[oo][seg * 16 + 8]);
}

// ---------------------------------------------------------------------------
// Main GEMM via mma.sync bf16 (3-pass hi/lo split), 4-stage cp.async pipeline.
// No in-loop conversion, no register staging. 512 threads, warp grid 4x4,
// warp tile 32x32. Grid: 128 CTAs = (64 m-tiles) x (2 j-halves).
// ---------------------------------------------------------------------------
__global__ __launch_bounds__(512, 1)
void graphconv_hmma_kernel(const float* __restrict__ bias,
                           float* __restrict__ out) {
    extern __shared__ __align__(16) char smem[];
    const uint32_t sbase = smem_u32(smem);

    const int t     = threadIdx.x;
    const int wid   = t >> 5;
    const int lane  = t & 31;
    const int mtile = blockIdx.x >> 1;
    const int jhalf = blockIdx.x & 1;
    const int n0    = mtile * BM;
    const int wrow  = wid >> 2;         // 0..3 -> 32 m rows each
    const int wcol  = wid & 3;          // 0..3 -> 32 n cols each

    // cp.async mapping: thread -> (row 0..127, one 16B chunk of the 64B row)
    const int row = t >> 2;
    const int ch  = t & 3;
    const uint32_t dstOff = row * (SK * 2) + ch * 16;
    const size_t aRow = (size_t)(n0 + row) * NN + ch * 8;
    const size_t bRow = (size_t)(jhalf * 128 + row) * NN + ch * 8;

    float acc[2][4][4];
#pragma unroll
    for (int i = 0; i < 2; i++)
#pragma unroll
        for (int j = 0; j < 4; j++)
#pragma unroll
            for (int p = 0; p < 4; p++) acc[i][j][p] = 0.0f;

    // ldmatrix per-thread byte offsets within a stage
    const int arow = wrow * 32 + (lane & 15);
    const int acol = (lane >> 4) * 8;
    const uint32_t aOff = arow * (SK * 2) + acol * 2;
    const int brow = wcol * 32 + (lane & 7) + ((lane >> 4) << 3);
    const int bcol = ((lane >> 3) & 1) << 3;
    const uint32_t bOff = brow * (SK * 2) + bcol * 2;

#define ISSUE(kt)                                                               \
    {                                                                           \
        const int sidx = (kt) >> 8;                                             \
        const int k0   = ((kt) & 255) * BK;                                     \
        const size_t aIdx = (size_t)sidx * NN * NN + aRow + k0;                 \
        const size_t bIdx = (size_t)sidx * JDIM * NN + bRow + k0;               \
        const uint32_t db = sbase + ((kt) & (NSTAGES - 1)) * ST_BYTES + dstOff; \
        cp_async16(db + AHI_OFF, g_A_hi + aIdx);                                \
        cp_async16(db + ALO_OFF, g_A_lo + aIdx);                                \
        cp_async16(db + BHI_OFF, g_Yt_hi + bIdx);                               \
        cp_async16(db + BLO_OFF, g_Yt_lo + bIdx);                               \
    }

    // ---- prologue: stages 0..2 in flight ----
    ISSUE(0); cp_commit();
    ISSUE(1); cp_commit();
    ISSUE(2); cp_commit();

#pragma unroll 4
    for (int kt = 0; kt < KT; kt++) {
        cp_wait2();            // stage kt retired (in-order groups)
        __syncthreads();       // all warps: stage kt visible; compute(kt-1) done

        // issue stage kt+3 into slot (kt-1)&3 (safe: compute(kt-1) complete)
        if (kt + 3 < KT) ISSUE(kt + 3);
        cp_commit();           // always commit (keeps group accounting exact)

        // ---- compute from stage kt&3 ----
        const uint32_t stage = sbase + (kt & (NSTAGES - 1)) * ST_BYTES;
        const uint32_t aHiAddr = stage + AHI_OFF + aOff;
        const uint32_t aLoAddr = stage + ALO_OFF + aOff;
        const uint32_t bHiAddr = stage + BHI_OFF + bOff;
        const uint32_t bLoAddr = stage + BLO_OFF + bOff;

#pragma unroll
        for (int ks = 0; ks < 2; ks++) {
            uint32_t afh[2][4], afl[2][4];
#pragma unroll
            for (int mt = 0; mt < 2; mt++) {
                ldsm4(afh[mt], aHiAddr + mt * (16 * SK * 2) + ks * 32);
                ldsm4(afl[mt], aLoAddr + mt * (16 * SK * 2) + ks * 32);
            }
            uint32_t bfh[2][4], bfl[2][4];
#pragma unroll
            for (int p = 0; p < 2; p++) {
                ldsm4(bfh[p], bHiAddr + p * (16 * SK * 2) + ks * 32);
                ldsm4(bfl[p], bLoAddr + p * (16 * SK * 2) + ks * 32);
            }
#pragma unroll
            for (int mt = 0; mt < 2; mt++) {
#pragma unroll
                for (int nt = 0; nt < 4; nt++) {
                    const uint32_t* bh = &bfh[nt >> 1][(nt & 1) * 2];
                    const uint32_t* bl = &bfl[nt >> 1][(nt & 1) * 2];
                    mma_bf16(acc[mt][nt], afh[mt], bh);
                    mma_bf16(acc[mt][nt], afh[mt], bl);
                    mma_bf16(acc[mt][nt], afl[mt], bh);
                }
            }
        }
    }

    // ---- epilogue: C frag -> out (+bias) ----
    // j = jhalf*128 + wcol*32 + (nt*8 + (lane&3)*2); b = j>>5, o = j&31
    {
        const int g    = lane >> 2;
        const int qq   = lane & 3;
        const int bidx = jhalf * 4 + wcol;
        float* obase = out + (size_t)bidx * NN * COUT;
#pragma unroll
        for (int mt = 0; mt < 2; mt++) {
            const int m = n0 + wrow * 32 + mt * 16 + g;
#pragma unroll
            for (int nt = 0; nt < 4; nt++) {
                const int o = nt * 8 + qq * 2;
                const float2 bv = *(const float2*)(bias + o);
                float2 v0, v1;
                v0.x = acc[mt][nt][0] + bv.x;
                v0.y = acc[mt][nt][1] + bv.y;
                v1.x = acc[mt][nt][2] + bv.x;
                v1.y = acc[mt][nt][3] + bv.y;
                *(float2*)(obase + (size_t)m * COUT + o)       = v0;
                *(float2*)(obase + (size_t)(m + 8) * COUT + o) = v1;
            }
        }
    }
}

// ---------------------------------------------------------------------------
extern "C" void kernel_launch(void* const* d_in, const int* in_sizes, int n_in,
                              void* d_out, int out_size) {
    const float* x        = (const float*)d_in[0];  // (8, 8192, 32)
    const float* supports = (const float*)d_in[1];  // (2, 8192, 8192)
    const float* W        = (const float*)d_in[2];  // (2, 32, 32)
    const float* bias     = (const float*)d_in[3];  // (32,)
    float* out = (float*)d_out;                     // (8, 8192, 32)
    (void)in_sizes; (void)n_in; (void)out_size;

    cudaFuncSetAttribute(graphconv_hmma_kernel,
                         cudaFuncAttributeMaxDynamicSharedMemorySize, SMEM_TOTAL);

    prep_Asplit_kernel<<<65536, 256>>>(supports);
    prep_Yt_kernel<<<dim3(64, 8, 2), 256>>>(x, W);
    graphconv_hmma_kernel<<<128, 512, SMEM_TOTAL>>>(bias, out);
}

// round 16
// speedup vs baseline: 1.3606x; 1.3606x over previous
#include <cuda_runtime.h>
#include <cuda_fp16.h>
#include <cstdint>

#define NN    8192
#define SDIM  2
#define JDIM  256
#define COUT  32

#define BM 128
#define BN 128
#define BK 32
#define KT 512          // SDIM*NN / BK
#define SK 40           // padded smem row stride in fp16 elems (80B, 16B-aligned)

// Pre-split B operand: Yt[s][j][k] = Y[s][k][j], fp16 hi/lo (8.4 MB each)
__device__ __align__(256) __half g_Yt_hi[(size_t)SDIM * JDIM * NN];
__device__ __align__(256) __half g_Yt_lo[(size_t)SDIM * JDIM * NN];

// ---------------------------------------------------------------------------
// helpers
// ---------------------------------------------------------------------------
__device__ __forceinline__ uint32_t smem_u32(const void* p) {
    uint32_t a;
    asm("{ .reg .u64 t; cvta.to.shared.u64 t, %1; cvt.u32.u64 %0, t; }"
        : "=r"(a) : "l"(p));
    return a;
}

// pack two floats to f16x2 (element0 = a, element1 = b)
__device__ __forceinline__ uint32_t h2(float a, float b) {
    uint32_t r;
    asm("cvt.rn.f16x2.f32 %0, %1, %2;" : "=r"(r) : "f"(b), "f"(a));
    return r;
}

__device__ __forceinline__ void ldsm4(uint32_t* r, uint32_t addr) {
    asm volatile("ldmatrix.sync.aligned.m8n8.x4.shared.b16 {%0,%1,%2,%3}, [%4];"
                 : "=r"(r[0]), "=r"(r[1]), "=r"(r[2]), "=r"(r[3]) : "r"(addr));
}

__device__ __forceinline__ void mma_f16(float* c, const uint32_t* a, const uint32_t* b) {
    asm volatile(
        "mma.sync.aligned.m16n8k16.row.col.f32.f16.f16.f32 "
        "{%0,%1,%2,%3},{%4,%5,%6,%7},{%8,%9},{%0,%1,%2,%3};"
        : "+f"(c[0]), "+f"(c[1]), "+f"(c[2]), "+f"(c[3])
        : "r"(a[0]), "r"(a[1]), "r"(a[2]), "r"(a[3]), "r"(b[0]), "r"(b[1]));
}

// ---------------------------------------------------------------------------
// Kernel A: Yt_hi/lo[s][j][k] = split_f16( sum_c x[b,k,c] * W[s,o,c] ),
//           j = b*32+o.  grid (64 kblocks, 8 b, 2 s), 256 threads.
// ---------------------------------------------------------------------------
__global__ void prep_Yt_kernel(const float* __restrict__ x,
                               const float* __restrict__ W) {
    __shared__ float Wsh[COUT][33];
    __shared__ __align__(16) float xsh[128][32];
    __shared__ __align__(16) __half yhi[COUT][128];
    __shared__ __align__(16) __half ylo[COUT][128];

    const int s  = blockIdx.z;
    const int b  = blockIdx.y;
    const int kb = blockIdx.x;
    const int t  = threadIdx.x;

    for (int i = t; i < 1024; i += 256) Wsh[i >> 5][i & 31] = W[s * 1024 + i];

    const float4* xbase = (const float4*)(x + ((size_t)b * NN + (size_t)kb * 128) * 32);
#pragma unroll
    for (int i = 0; i < 4; i++) {
        int f = t + 256 * i;
        ((float4*)&xsh[0][0])[f] = xbase[f];
    }
    __syncthreads();

    const int o = t & 31;
#pragma unroll
    for (int i = 0; i < 16; i++) {
        int ki = (t >> 5) + i * 8;
        float sum = 0.0f;
#pragma unroll
        for (int c = 0; c < 32; c++) sum += xsh[ki][c] * Wsh[o][c];
        __half hv = __float2half_rn(sum);
        float hf = __half2float(hv);
        __half lv = __float2half_rn(sum - hf);
        yhi[o][ki] = hv;
        ylo[o][ki] = lv;
    }
    __syncthreads();

    // writeback: each thread owns 16 elements = TWO uint4 (uint4 = 8 fp16)
    const int oo  = t >> 3;
    const int seg = t & 7;
    size_t base = ((size_t)(s * JDIM + b * 32 + oo)) * NN + (size_t)kb * 128 + seg * 16;
    *(uint4*)(&g_Yt_hi[base])     = *(const uint4*)(&yhi[oo][seg * 16]);
    *(uint4*)(&g_Yt_hi[base + 8]) = *(const uint4*)(&yhi[oo][seg * 16 + 8]);
    *(uint4*)(&g_Yt_lo[base])     = *(const uint4*)(&ylo[oo][seg * 16]);
    *(uint4*)(&g_Yt_lo[base + 8]) = *(const uint4*)(&ylo[oo][seg * 16 + 8]);
}

// ---------------------------------------------------------------------------
// Main GEMM via mma.sync fp16, TWO passes: out = A_f16 * (B_hi + B_lo).
// R5's measured-best structure: 256 threads, 8 warps (2x4), warp tile 64x32,
// single smem buffer, 2-sync loop, register prefetch.
// Grid: 128 CTAs = (64 m-tiles) x (2 j-halves).
// ---------------------------------------------------------------------------
__global__ __launch_bounds__(256, 1)
void graphconv_hmma_kernel(const float* __restrict__ supports,
                           const float* __restrict__ bias,
                           float* __restrict__ out) {
    __shared__ __align__(16) __half Ah [BM][SK];
    __shared__ __align__(16) __half Bhi[BN][SK];
    __shared__ __align__(16) __half Blo[BN][SK];

    const int t     = threadIdx.x;
    const int wid   = t >> 5;
    const int lane  = t & 31;
    const int mtile = blockIdx.x >> 1;
    const int jhalf = blockIdx.x & 1;
    const int n0    = mtile * BM;
    const int wrow  = wid >> 2;         // 0..1 -> 64 m rows each
    const int wcol  = wid & 3;          // 0..3 -> 32 n cols each

    // gmem load mapping: each thread owns half a row (16 k elems)
    const int row  = t >> 1;            // 0..127
    const int koff = (t & 1) * 16;      // 0 or 16

    float4 ra[4];                       // 16 fp32 A elems
    uint4  rbh[2], rbl[2];              // 16 fp16 hi + 16 fp16 lo B elems

    float acc[4][4][4];
#pragma unroll
    for (int i = 0; i < 4; i++)
#pragma unroll
        for (int j = 0; j < 4; j++)
#pragma unroll
            for (int p = 0; p < 4; p++) acc[i][j][p] = 0.0f;

    // ldmatrix source addresses (per thread, fixed parts)
    const int arow = wrow * 64 + (lane & 15);
    const int acol = (lane >> 4) * 8;
    const uint32_t aAddr = smem_u32(&Ah[arow][acol]);
    const int brow = wcol * 32 + (lane & 7) + ((lane >> 4) << 3);
    const int bcol = ((lane >> 3) & 1) << 3;
    const uint32_t bHiAddr = smem_u32(&Bhi[brow][bcol]);
    const uint32_t bLoAddr = smem_u32(&Blo[brow][bcol]);

#define LOAD_A(kt)                                                              \
    {                                                                           \
        const int sidx = (kt) >> 8;                                             \
        const int k0   = ((kt) & 255) * BK;                                     \
        const float* ap = supports + (size_t)sidx * NN * NN                     \
                        + (size_t)(n0 + row) * NN + k0 + koff;                  \
        ra[0] = *(const float4*)(ap + 0);                                       \
        ra[1] = *(const float4*)(ap + 4);                                       \
        ra[2] = *(const float4*)(ap + 8);                                       \
        ra[3] = *(const float4*)(ap + 12);                                      \
    }

#define LOAD_B(kt)                                                              \
    {                                                                           \
        const int sidx = (kt) >> 8;                                             \
        const int k0   = ((kt) & 255) * BK;                                     \
        const size_t boff = ((size_t)(sidx * JDIM + jhalf * 128 + row)) * NN    \
                          + k0 + koff;                                          \
        rbh[0] = *(const uint4*)(g_Yt_hi + boff);                               \
        rbh[1] = *(const uint4*)(g_Yt_hi + boff + 8);                           \
        rbl[0] = *(const uint4*)(g_Yt_lo + boff);                               \
        rbl[1] = *(const uint4*)(g_Yt_lo + boff + 8);                           \
    }

    LOAD_A(0);
    LOAD_B(0);

    for (int kt = 0; kt < KT; kt++) {
        __syncthreads();   // previous compute done before overwriting smem

        // ---- STS: convert A to single fp16, store B hi/lo directly ----
        {
            uint32_t a01 = h2(ra[0].x, ra[0].y);
            uint32_t a23 = h2(ra[0].z, ra[0].w);
            uint32_t a45 = h2(ra[1].x, ra[1].y);
            uint32_t a67 = h2(ra[1].z, ra[1].w);
            uint32_t a89 = h2(ra[2].x, ra[2].y);
            uint32_t aAB = h2(ra[2].z, ra[2].w);
            uint32_t aCD = h2(ra[3].x, ra[3].y);
            uint32_t aEF = h2(ra[3].z, ra[3].w);
            *(uint4*)&Ah[row][koff]     = make_uint4(a01, a23, a45, a67);
            *(uint4*)&Ah[row][koff + 8] = make_uint4(a89, aAB, aCD, aEF);
            *(uint4*)&Bhi[row][koff]     = rbh[0];
            *(uint4*)&Bhi[row][koff + 8] = rbh[1];
            *(uint4*)&Blo[row][koff]     = rbl[0];
            *(uint4*)&Blo[row][koff + 8] = rbl[1];
        }
        __syncthreads();

        // ---- prefetch next tile into regs (overlaps with compute) ----
        if (kt + 1 < KT) {
            LOAD_A(kt + 1);
            LOAD_B(kt + 1);
        }

        // ---- compute: 2 k-steps of 16 ----
#pragma unroll
        for (int ks = 0; ks < 2; ks++) {
            uint32_t af[4][4];
#pragma unroll
            for (int mt = 0; mt < 4; mt++)
                ldsm4(af[mt], aAddr + mt * (16 * SK * 2) + ks * 32);
            uint32_t bfh[2][4], bfl[2][4];
#pragma unroll
            for (int p = 0; p < 2; p++) {
                ldsm4(bfh[p], bHiAddr + p * (16 * SK * 2) + ks * 32);
                ldsm4(bfl[p], bLoAddr + p * (16 * SK * 2) + ks * 32);
            }
#pragma unroll
            for (int mt = 0; mt < 4; mt++) {
#pragma unroll
                for (int nt = 0; nt < 4; nt++) {
                    const uint32_t* bh = &bfh[nt >> 1][(nt & 1) * 2];
                    const uint32_t* bl = &bfl[nt >> 1][(nt & 1) * 2];
                    mma_f16(acc[mt][nt], af[mt], bh);
                    mma_f16(acc[mt][nt], af[mt], bl);
                }
            }
        }
    }

    // ---- epilogue: C frag -> out (+bias) ----
    // j = jhalf*128 + wcol*32 + (nt*8 + (lane&3)*2); b = j>>5, o = j&31
    {
        const int g    = lane >> 2;
        const int qq   = lane & 3;
        const int bidx = jhalf * 4 + wcol;
        float* obase = out + (size_t)bidx * NN * COUT;
#pragma unroll
        for (int mt = 0; mt < 4; mt++) {
            const int m = n0 + wrow * 64 + mt * 16 + g;
#pragma unroll
            for (int nt = 0; nt < 4; nt++) {
                const int o = nt * 8 + qq * 2;
                const float2 bv = *(const float2*)(bias + o);
                float2 v0, v1;
                v0.x = acc[mt][nt][0] + bv.x;
                v0.y = acc[mt][nt][1] + bv.y;
                v1.x = acc[mt][nt][2] + bv.x;
                v1.y = acc[mt][nt][3] + bv.y;
                *(float2*)(obase + (size_t)m * COUT + o)       = v0;
                *(float2*)(obase + (size_t)(m + 8) * COUT + o) = v1;
            }
        }
    }
}

// ---------------------------------------------------------------------------
extern "C" void kernel_launch(void* const* d_in, const int* in_sizes, int n_in,
                              void* d_out, int out_size) {
    const float* x        = (const float*)d_in[0];  // (8, 8192, 32)
    const float* supports = (const float*)d_in[1];  // (2, 8192, 8192)
    const float* W        = (const float*)d_in[2];  // (2, 32, 32)
    const float* bias     = (const float*)d_in[3];  // (32,)
    float* out = (float*)d_out;                     // (8, 8192, 32)
    (void)in_sizes; (void)n_in; (void)out_size;

    prep_Yt_kernel<<<dim3(64, 8, 2), 256>>>(x, W);
    graphconv_hmma_kernel<<<128, 256>>>(supports, bias, out);
}